// round 2
// baseline (speedup 1.0000x reference)
#include <cuda_runtime.h>
#include <cuda_bf16.h>

#define D       128
#define MAXN    100000
#define MAXE    1600000

typedef unsigned long long u64;

// ---------------------------------------------------------------------------
// Scratch (static __device__ arrays: no allocation allowed)
// ---------------------------------------------------------------------------
__device__ int   g_deg[MAXN];
__device__ float g_scale[MAXN];                   // rsqrt(deg+1)
__device__ float g_inv[MAXN];                     // 1/max(deg,1)
__device__ int   g_rowstart[MAXN];                // CSR row offsets (exclusive scan of deg)
__device__ int   g_cursor[MAXN];                  // fill cursors
__device__ int   g_csr[MAXE];                     // src indices grouped by dst
__device__ int   g_part[1024];                    // scan partials
__device__ float g_pre[(size_t)MAXN * D];         // (feat*scale) @ W   (51.2 MB)

// ---------------------------------------------------------------------------
__global__ void init_kernel(int n) {
    int i = blockIdx.x * blockDim.x + threadIdx.x;
    if (i < n) g_deg[i] = 0;
}

__global__ void deg_kernel(const int* __restrict__ dst, int E) {
    int i = blockIdx.x * blockDim.x + threadIdx.x;
    if (i < E) atomicAdd(&g_deg[dst[i]], 1);
}

__global__ void scale_kernel(int n) {
    int i = blockIdx.x * blockDim.x + threadIdx.x;
    if (i < n) {
        int d = g_deg[i];
        g_scale[i] = rsqrtf((float)d + 1.0f);
        g_inv[i]   = 1.0f / (float)(d > 0 ? d : 1);
    }
}

// ---------------------------------------------------------------------------
// 3-kernel exclusive scan of g_deg -> g_rowstart (1024 elems / block)
// ---------------------------------------------------------------------------
__global__ void scan_part(int n) {
    int tid = threadIdx.x;
    int base = blockIdx.x * 1024 + tid * 4;
    int s = 0;
#pragma unroll
    for (int i = 0; i < 4; i++) {
        int idx = base + i;
        s += (idx < n) ? g_deg[idx] : 0;
    }
    __shared__ int sh[256];
    sh[tid] = s;
    __syncthreads();
    for (int off = 128; off > 0; off >>= 1) {
        if (tid < off) sh[tid] += sh[tid + off];
        __syncthreads();
    }
    if (tid == 0) g_part[blockIdx.x] = sh[0];
}

__global__ void scan_mid(int nblk) {
    // single block, 1024 threads: exclusive scan of g_part
    __shared__ int sh[1024];
    int tid = threadIdx.x;
    int v = (tid < nblk) ? g_part[tid] : 0;
    sh[tid] = v;
    __syncthreads();
    for (int off = 1; off < 1024; off <<= 1) {
        int t = (tid >= off) ? sh[tid - off] : 0;
        __syncthreads();
        sh[tid] += t;
        __syncthreads();
    }
    if (tid < nblk) g_part[tid] = sh[tid] - v;   // exclusive
}

__global__ void scan_final(int n) {
    int tid = threadIdx.x;
    int base = blockIdx.x * 1024 + tid * 4;
    int vals[4];
    int s = 0;
#pragma unroll
    for (int i = 0; i < 4; i++) {
        int idx = base + i;
        vals[i] = (idx < n) ? g_deg[idx] : 0;
        s += vals[i];
    }
    __shared__ int sh[256];
    sh[tid] = s;
    __syncthreads();
    for (int off = 1; off < 256; off <<= 1) {
        int t = (tid >= off) ? sh[tid - off] : 0;
        __syncthreads();
        sh[tid] += t;
        __syncthreads();
    }
    int run = g_part[blockIdx.x] + (sh[tid] - s);   // exclusive offset for this thread
#pragma unroll
    for (int i = 0; i < 4; i++) {
        int idx = base + i;
        if (idx < n) {
            g_rowstart[idx] = run;
            g_cursor[idx]   = run;
            run += vals[i];
        }
    }
}

// ---------------------------------------------------------------------------
// CSR fill: bucket src by dst
// ---------------------------------------------------------------------------
__global__ void fill_kernel(const int* __restrict__ src,
                            const int* __restrict__ dst, int E) {
    int i = blockIdx.x * blockDim.x + threadIdx.x;
    if (i < E) {
        int p = atomicAdd(&g_cursor[dst[i]], 1);
        g_csr[p] = src[i];
    }
}

// ---------------------------------------------------------------------------
// GEMM: g_pre[n, 128] = (feature[n,:] * scale[n]) @ W[128,128]
// BM=128, BN=128, BK=16, 256 threads, 8x8 tiles, packed f32x2 FMA.
// ---------------------------------------------------------------------------
#define BM 128
#define BN 128
#define BK 16
#define TM 8
#define TN 8

__device__ __forceinline__ u64 pack2(float lo, float hi) {
    u64 r;
    asm("mov.b64 %0, {%1,%2};" : "=l"(r) : "f"(lo), "f"(hi));
    return r;
}
__device__ __forceinline__ float2 unpack2(u64 v) {
    float2 r;
    asm("mov.b64 {%0,%1}, %2;" : "=f"(r.x), "=f"(r.y) : "l"(v));
    return r;
}
__device__ __forceinline__ void fma2(u64& c, u64 a, u64 b) {
    asm("fma.rn.f32x2 %0, %1, %2, %3;" : "=l"(c) : "l"(a), "l"(b), "l"(c));
}

__global__ __launch_bounds__(256, 2)
void gemm_kernel(const float* __restrict__ feat,
                 const float* __restrict__ W,
                 float* __restrict__ pre,
                 int n) {
    __shared__ __align__(16) float As[BK][BM + 4];
    __shared__ __align__(16) float Ws[BK][BN];

    int block_row = blockIdx.x * BM;
    int tid = threadIdx.x;
    int tx = tid & 15;          // 0..15 -> col groups of 8
    int ty = tid >> 4;          // 0..15 -> row groups of 8

    u64 c2[TM][TN / 2];
#pragma unroll
    for (int i = 0; i < TM; i++)
#pragma unroll
        for (int j = 0; j < TN / 2; j++) c2[i][j] = 0ULL;

    for (int k0 = 0; k0 < D; k0 += BK) {
        // Load A tile (BM x BK), applying scale at load.
#pragma unroll
        for (int it = 0; it < 2; it++) {
            int idx = tid + it * 256;       // 0..511
            int row = idx >> 2;             // 0..127
            int k4  = (idx & 3) * 4;        // 0,4,8,12
            int grow = block_row + row;
            float4 v = make_float4(0.f, 0.f, 0.f, 0.f);
            float sc = 0.f;
            if (grow < n) {
                v  = __ldg((const float4*)&feat[(size_t)grow * D + k0 + k4]);
                sc = g_scale[grow];
            }
            As[k4 + 0][row] = v.x * sc;
            As[k4 + 1][row] = v.y * sc;
            As[k4 + 2][row] = v.z * sc;
            As[k4 + 3][row] = v.w * sc;
        }
        // Load W tile (BK x BN).
#pragma unroll
        for (int it = 0; it < 2; it++) {
            int idx = tid + it * 256;       // 0..511
            int k  = idx >> 5;              // 0..15
            int c4 = (idx & 31) * 4;        // 0..124
            float4 v = __ldg((const float4*)&W[(size_t)(k0 + k) * D + c4]);
            *(float4*)&Ws[k][c4] = v;
        }
        __syncthreads();

#pragma unroll
        for (int k = 0; k < BK; k++) {
            u64 ap[TM], wv[TN / 2];
#pragma unroll
            for (int i = 0; i < TM; i++) {
                float a = As[k][ty * TM + i];
                ap[i] = pack2(a, a);
            }
            const u64* wp = (const u64*)&Ws[k][tx * TN];
#pragma unroll
            for (int j = 0; j < TN / 2; j++) wv[j] = wp[j];
#pragma unroll
            for (int i = 0; i < TM; i++)
#pragma unroll
                for (int j = 0; j < TN / 2; j++)
                    fma2(c2[i][j], ap[i], wv[j]);
        }
        __syncthreads();
    }

    // Epilogue: write pre (no bias here — bias added in aggregation)
#pragma unroll
    for (int i = 0; i < TM; i++) {
        int row = block_row + ty * TM + i;
        if (row < n) {
            float2 p0 = unpack2(c2[i][0]);
            float2 p1 = unpack2(c2[i][1]);
            float2 p2 = unpack2(c2[i][2]);
            float2 p3 = unpack2(c2[i][3]);
            int col = tx * TN;
            *(float4*)&pre[(size_t)row * D + col]     = make_float4(p0.x, p0.y, p1.x, p1.y);
            *(float4*)&pre[(size_t)row * D + col + 4] = make_float4(p2.x, p2.y, p3.x, p3.y);
        }
    }
}

// ---------------------------------------------------------------------------
// Aggregation (gather): one warp per dst node.
// out[d,:] = inv[d] * sum_{s in nbr(d)} pre[s,:] + bias
// ---------------------------------------------------------------------------
__global__ __launch_bounds__(256)
void agg_kernel(const float* __restrict__ pre,
                const float* __restrict__ bias,
                float* __restrict__ out,
                int N) {
    int t = blockIdx.x * blockDim.x + threadIdx.x;
    int node = t >> 5;
    int lane = t & 31;
    if (node >= N) return;

    int start = g_rowstart[node];
    int deg   = g_deg[node];
    int end   = start + deg;

    float4 acc = make_float4(0.f, 0.f, 0.f, 0.f);

    int j = start;
    // unroll-4 for MLP
    for (; j + 3 < end; j += 4) {
        int s0 = __ldg(&g_csr[j + 0]);
        int s1 = __ldg(&g_csr[j + 1]);
        int s2 = __ldg(&g_csr[j + 2]);
        int s3 = __ldg(&g_csr[j + 3]);
        float4 v0 = __ldg((const float4*)(pre + (size_t)s0 * D) + lane);
        float4 v1 = __ldg((const float4*)(pre + (size_t)s1 * D) + lane);
        float4 v2 = __ldg((const float4*)(pre + (size_t)s2 * D) + lane);
        float4 v3 = __ldg((const float4*)(pre + (size_t)s3 * D) + lane);
        acc.x += v0.x + v1.x + v2.x + v3.x;
        acc.y += v0.y + v1.y + v2.y + v3.y;
        acc.z += v0.z + v1.z + v2.z + v3.z;
        acc.w += v0.w + v1.w + v2.w + v3.w;
    }
    for (; j < end; j++) {
        int s = __ldg(&g_csr[j]);
        float4 v = __ldg((const float4*)(pre + (size_t)s * D) + lane);
        acc.x += v.x; acc.y += v.y; acc.z += v.z; acc.w += v.w;
    }

    float iv = g_inv[node];
    float4 bb = __ldg((const float4*)bias + lane);
    float4 r;
    r.x = acc.x * iv + bb.x;
    r.y = acc.y * iv + bb.y;
    r.z = acc.z * iv + bb.z;
    r.w = acc.w * iv + bb.w;
    *((float4*)(out + (size_t)node * D) + lane) = r;
}

// ---------------------------------------------------------------------------
extern "C" void kernel_launch(void* const* d_in, const int* in_sizes, int n_in,
                              void* d_out, int out_size) {
    const float* feature = (const float*)d_in[0];
    const float* W       = (const float*)d_in[1];
    const float* bias    = (const float*)d_in[2];
    const int*   src     = (const int*)d_in[3];
    const int*   dst     = (const int*)d_in[4];
    float*       out     = (float*)d_out;

    int N = in_sizes[0] / D;
    int E = in_sizes[3];

    int nblk_scan = (N + 1023) / 1024;

    // 1) zero degree
    init_kernel<<<(N + 255) / 256, 256>>>(N);
    // 2) in-degree histogram
    deg_kernel<<<(E + 255) / 256, 256>>>(dst, E);
    // 3) per-node scale factors
    scale_kernel<<<(N + 255) / 256, 256>>>(N);
    // 4) exclusive scan -> rowstart / cursor
    scan_part<<<nblk_scan, 256>>>(N);
    scan_mid<<<1, 1024>>>(nblk_scan);
    scan_final<<<nblk_scan, 256>>>(N);
    // 5) CSR fill
    fill_kernel<<<(E + 255) / 256, 256>>>(src, dst, E);
    // 6) GEMM: pre = (feat * scale) @ W
    gemm_kernel<<<(N + BM - 1) / BM, 256>>>(feature, W, g_pre, N);
    // 7) gather aggregation + inv + bias
    {
        long long total = (long long)N * 32;
        int blocks = (int)((total + 255) / 256);
        agg_kernel<<<blocks, 256>>>(g_pre, bias, out, N);
    }
}

// round 4
// speedup vs baseline: 1.0083x; 1.0083x over previous
#include <cuda_runtime.h>
#include <cuda_bf16.h>

#define D       128
#define MAXN    100000
#define MAXE    1600000

// ---------------------------------------------------------------------------
// Scratch (static __device__ arrays: no allocation allowed)
// ---------------------------------------------------------------------------
__device__ int   g_deg[MAXN];
__device__ float g_scale[MAXN];                   // rsqrt(deg+1)
__device__ float g_inv[MAXN];                     // 1/max(deg,1)
__device__ int   g_rowstart[MAXN];                // CSR row offsets
__device__ int   g_cursor[MAXN];                  // fill cursors
__device__ int   g_csr[MAXE];                     // src indices grouped by dst
__device__ int   g_part[1024];                    // scan partials
__device__ float g_pre[(size_t)MAXN * D];         // (feat*scale) @ W   (51.2 MB)

// ---------------------------------------------------------------------------
__global__ void init_kernel(int n) {
    int i = blockIdx.x * blockDim.x + threadIdx.x;
    if (i < n) g_deg[i] = 0;
}

__global__ void deg_kernel(const int* __restrict__ dst, int E) {
    int i = blockIdx.x * blockDim.x + threadIdx.x;
    if (i < E) atomicAdd(&g_deg[dst[i]], 1);
}

__global__ void scale_kernel(int n) {
    int i = blockIdx.x * blockDim.x + threadIdx.x;
    if (i < n) {
        int d = g_deg[i];
        g_scale[i] = rsqrtf((float)d + 1.0f);
        g_inv[i]   = 1.0f / (float)(d > 0 ? d : 1);
    }
}

// ---------------------------------------------------------------------------
// 3-kernel exclusive scan of g_deg -> g_rowstart (1024 elems / block)
// ---------------------------------------------------------------------------
__global__ void scan_part(int n) {
    int tid = threadIdx.x;
    int base = blockIdx.x * 1024 + tid * 4;
    int s = 0;
#pragma unroll
    for (int i = 0; i < 4; i++) {
        int idx = base + i;
        s += (idx < n) ? g_deg[idx] : 0;
    }
    __shared__ int sh[256];
    sh[tid] = s;
    __syncthreads();
    for (int off = 128; off > 0; off >>= 1) {
        if (tid < off) sh[tid] += sh[tid + off];
        __syncthreads();
    }
    if (tid == 0) g_part[blockIdx.x] = sh[0];
}

__global__ void scan_mid(int nblk) {
    __shared__ int sh[1024];
    int tid = threadIdx.x;
    int v = (tid < nblk) ? g_part[tid] : 0;
    sh[tid] = v;
    __syncthreads();
    for (int off = 1; off < 1024; off <<= 1) {
        int t = (tid >= off) ? sh[tid - off] : 0;
        __syncthreads();
        sh[tid] += t;
        __syncthreads();
    }
    if (tid < nblk) g_part[tid] = sh[tid] - v;   // exclusive
}

__global__ void scan_final(int n) {
    int tid = threadIdx.x;
    int base = blockIdx.x * 1024 + tid * 4;
    int vals[4];
    int s = 0;
#pragma unroll
    for (int i = 0; i < 4; i++) {
        int idx = base + i;
        vals[i] = (idx < n) ? g_deg[idx] : 0;
        s += vals[i];
    }
    __shared__ int sh[256];
    sh[tid] = s;
    __syncthreads();
    for (int off = 1; off < 256; off <<= 1) {
        int t = (tid >= off) ? sh[tid - off] : 0;
        __syncthreads();
        sh[tid] += t;
        __syncthreads();
    }
    int run = g_part[blockIdx.x] + (sh[tid] - s);
#pragma unroll
    for (int i = 0; i < 4; i++) {
        int idx = base + i;
        if (idx < n) {
            g_rowstart[idx] = run;
            g_cursor[idx]   = run;
            run += vals[i];
        }
    }
}

// ---------------------------------------------------------------------------
__global__ void fill_kernel(const int* __restrict__ src,
                            const int* __restrict__ dst, int E) {
    int i = blockIdx.x * blockDim.x + threadIdx.x;
    if (i < E) {
        int p = atomicAdd(&g_cursor[dst[i]], 1);
        g_csr[p] = src[i];
    }
}

// ---------------------------------------------------------------------------
// GEMM: g_pre[n, 128] = (feature[n,:] * scale[n]) @ W[128,128]
// Round-1 proven FFMA version: float accumulators, 64 regs for C.
// ---------------------------------------------------------------------------
#define BM 128
#define BN 128
#define BK 16
#define TM 8
#define TN 8

__global__ __launch_bounds__(256, 2)
void gemm_kernel(const float* __restrict__ feat,
                 const float* __restrict__ W,
                 float* __restrict__ pre,
                 int n) {
    __shared__ float As[BK][BM + 4];
    __shared__ float Ws[BK][BN];

    int block_row = blockIdx.x * BM;
    int tid = threadIdx.x;
    int tx = tid & 15;
    int ty = tid >> 4;

    float c[TM][TN];
#pragma unroll
    for (int i = 0; i < TM; i++)
#pragma unroll
        for (int j = 0; j < TN; j++) c[i][j] = 0.f;

    for (int k0 = 0; k0 < D; k0 += BK) {
        // Load A tile (BM x BK), applying scale at load.
#pragma unroll
        for (int it = 0; it < 2; it++) {
            int idx = tid + it * 256;
            int row = idx >> 2;
            int k4  = (idx & 3) * 4;
            int grow = block_row + row;
            float4 v = make_float4(0.f, 0.f, 0.f, 0.f);
            float sc = 0.f;
            if (grow < n) {
                v  = __ldg((const float4*)&feat[(size_t)grow * D + k0 + k4]);
                sc = g_scale[grow];
            }
            As[k4 + 0][row] = v.x * sc;
            As[k4 + 1][row] = v.y * sc;
            As[k4 + 2][row] = v.z * sc;
            As[k4 + 3][row] = v.w * sc;
        }
        // Load W tile (BK x BN).
#pragma unroll
        for (int it = 0; it < 2; it++) {
            int idx = tid + it * 256;
            int k  = idx >> 5;
            int c4 = (idx & 31) * 4;
            float4 v = __ldg((const float4*)&W[(size_t)(k0 + k) * D + c4]);
            *(float4*)&Ws[k][c4] = v;
        }
        __syncthreads();

#pragma unroll
        for (int k = 0; k < BK; k++) {
            float a[TM], w[TN];
#pragma unroll
            for (int i = 0; i < TM; i++) a[i] = As[k][ty * TM + i];
#pragma unroll
            for (int j = 0; j < TN; j++) w[j] = Ws[k][tx * TN + j];
#pragma unroll
            for (int i = 0; i < TM; i++)
#pragma unroll
                for (int j = 0; j < TN; j++)
                    c[i][j] = fmaf(a[i], w[j], c[i][j]);
        }
        __syncthreads();
    }

#pragma unroll
    for (int i = 0; i < TM; i++) {
        int row = block_row + ty * TM + i;
        if (row < n) {
#pragma unroll
            for (int j = 0; j < TN; j += 4) {
                int col = tx * TN + j;
                float4 r = make_float4(c[i][j], c[i][j+1], c[i][j+2], c[i][j+3]);
                *(float4*)&pre[(size_t)row * D + col] = r;
            }
        }
    }
}

// ---------------------------------------------------------------------------
// Aggregation (gather): one warp per dst node.
// out[d,:] = inv[d] * sum_{s in nbr(d)} pre[s,:] + bias
// ---------------------------------------------------------------------------
__global__ __launch_bounds__(256)
void agg_kernel(const float* __restrict__ pre,
                const float* __restrict__ bias,
                float* __restrict__ out,
                int N) {
    int t = blockIdx.x * blockDim.x + threadIdx.x;
    int node = t >> 5;
    int lane = t & 31;
    if (node >= N) return;

    int start = g_rowstart[node];
    int deg   = g_deg[node];
    int end   = start + deg;

    float4 acc = make_float4(0.f, 0.f, 0.f, 0.f);

    int j = start;
    for (; j + 3 < end; j += 4) {
        int s0 = __ldg(&g_csr[j + 0]);
        int s1 = __ldg(&g_csr[j + 1]);
        int s2 = __ldg(&g_csr[j + 2]);
        int s3 = __ldg(&g_csr[j + 3]);
        float4 v0 = __ldg((const float4*)(pre + (size_t)s0 * D) + lane);
        float4 v1 = __ldg((const float4*)(pre + (size_t)s1 * D) + lane);
        float4 v2 = __ldg((const float4*)(pre + (size_t)s2 * D) + lane);
        float4 v3 = __ldg((const float4*)(pre + (size_t)s3 * D) + lane);
        acc.x += v0.x + v1.x + v2.x + v3.x;
        acc.y += v0.y + v1.y + v2.y + v3.y;
        acc.z += v0.z + v1.z + v2.z + v3.z;
        acc.w += v0.w + v1.w + v2.w + v3.w;
    }
    for (; j < end; j++) {
        int s = __ldg(&g_csr[j]);
        float4 v = __ldg((const float4*)(pre + (size_t)s * D) + lane);
        acc.x += v.x; acc.y += v.y; acc.z += v.z; acc.w += v.w;
    }

    float iv = g_inv[node];
    float4 bb = __ldg((const float4*)bias + lane);
    float4 r;
    r.x = acc.x * iv + bb.x;
    r.y = acc.y * iv + bb.y;
    r.z = acc.z * iv + bb.z;
    r.w = acc.w * iv + bb.w;
    *((float4*)(out + (size_t)node * D) + lane) = r;
}

// ---------------------------------------------------------------------------
extern "C" void kernel_launch(void* const* d_in, const int* in_sizes, int n_in,
                              void* d_out, int out_size) {
    const float* feature = (const float*)d_in[0];
    const float* W       = (const float*)d_in[1];
    const float* bias    = (const float*)d_in[2];
    const int*   src     = (const int*)d_in[3];
    const int*   dst     = (const int*)d_in[4];
    float*       out     = (float*)d_out;

    int N = in_sizes[0] / D;
    int E = in_sizes[3];

    int nblk_scan = (N + 1023) / 1024;

    init_kernel<<<(N + 255) / 256, 256>>>(N);
    deg_kernel<<<(E + 255) / 256, 256>>>(dst, E);
    scale_kernel<<<(N + 255) / 256, 256>>>(N);
    scan_part<<<nblk_scan, 256>>>(N);
    scan_mid<<<1, 1024>>>(nblk_scan);
    scan_final<<<nblk_scan, 256>>>(N);
    fill_kernel<<<(E + 255) / 256, 256>>>(src, dst, E);
    gemm_kernel<<<(N + BM - 1) / BM, 256>>>(feature, W, g_pre, N);
    {
        long long total = (long long)N * 32;
        int blocks = (int)((total + 255) / 256);
        agg_kernel<<<blocks, 256>>>(g_pre, bias, out, N);
    }
}

// round 5
// speedup vs baseline: 20.5357x; 20.3673x over previous
#include <cuda_runtime.h>
#include <cuda_bf16.h>

#define D       128
#define MAXN    100000
#define MAXE    1600000

// ---------------------------------------------------------------------------
// Scratch — static __device__ arrays, referenced ONLY inside kernels.
// (Passing these as kernel args from host resolves to the host shadow symbol,
//  which GB300's ATS happily serves over NVLink-C2C at 200GB/s — the round-2/4
//  5ms regression. Never again.)
// ---------------------------------------------------------------------------
__device__ int   g_deg[MAXN];
__device__ float g_inv[MAXN];                      // 1/max(deg,1)
__device__ int   g_rowstart[MAXN];
__device__ int   g_cursor[MAXN];
__device__ int   g_csr[MAXE];                      // src ids grouped by dst
__device__ int   g_total;                          // rowstart allocator
__device__ float g_pref[(size_t)MAXN * D];         // feat * rsqrt(deg+1)  (51.2MB)
__device__ float g_accum[(size_t)MAXN * D];        // gathered sums        (51.2MB)

// ---------------------------------------------------------------------------
// 0) In-degree histogram (g_deg zeroed by previous replay's gemm tail;
//    zero-initialized at module load for the very first run)
// ---------------------------------------------------------------------------
__global__ void deg_kernel(const int* __restrict__ dst, int E) {
    int i = blockIdx.x * blockDim.x + threadIdx.x;
    if (i < E) atomicAdd(&g_deg[dst[i]], 1);
}

// ---------------------------------------------------------------------------
// 1) prep: one warp per node.
//    g_pref[node,:] = feature[node,:] * rsqrt(deg+1)
//    lane 0: g_inv, rowstart = atomicAdd(&g_total, deg), cursor = rowstart
// ---------------------------------------------------------------------------
__global__ __launch_bounds__(256)
void prep_kernel(const float* __restrict__ feat, int N) {
    int t = blockIdx.x * blockDim.x + threadIdx.x;
    int node = t >> 5;
    int lane = t & 31;
    if (node >= N) return;

    int dg = g_deg[node];                 // broadcast within warp
    float sc = rsqrtf((float)dg + 1.0f);

    float4 v = __ldg((const float4*)(feat + (size_t)node * D) + lane);
    v.x *= sc; v.y *= sc; v.z *= sc; v.w *= sc;
    *((float4*)(g_pref + (size_t)node * D) + lane) = v;

    if (lane == 0) {
        g_inv[node] = 1.0f / (float)(dg > 0 ? dg : 1);
        int rs = atomicAdd(&g_total, dg);
        g_rowstart[node] = rs;
        g_cursor[node]   = rs;
    }
}

// ---------------------------------------------------------------------------
// 2) CSR fill: bucket src by dst
// ---------------------------------------------------------------------------
__global__ void fill_kernel(const int* __restrict__ src,
                            const int* __restrict__ dst, int E) {
    int i = blockIdx.x * blockDim.x + threadIdx.x;
    if (i < E) {
        int p = atomicAdd(&g_cursor[dst[i]], 1);
        g_csr[p] = src[i];
    }
}

// ---------------------------------------------------------------------------
// 3) Aggregation (pure gather): one warp per dst node.
//    g_accum[d,:] = sum_{s in nbr(d)} g_pref[s,:]
// ---------------------------------------------------------------------------
__global__ __launch_bounds__(256)
void agg_kernel(int N) {
    int t = blockIdx.x * blockDim.x + threadIdx.x;
    int node = t >> 5;
    int lane = t & 31;
    if (node >= N) return;

    int start = g_rowstart[node];
    int deg   = g_deg[node];
    int end   = start + deg;

    const float4* pre4 = (const float4*)g_pref;

    float4 acc = make_float4(0.f, 0.f, 0.f, 0.f);

    int j = start;
    for (; j + 3 < end; j += 4) {
        int s0 = __ldg(&g_csr[j + 0]);
        int s1 = __ldg(&g_csr[j + 1]);
        int s2 = __ldg(&g_csr[j + 2]);
        int s3 = __ldg(&g_csr[j + 3]);
        float4 v0 = __ldg(pre4 + (size_t)s0 * 32 + lane);
        float4 v1 = __ldg(pre4 + (size_t)s1 * 32 + lane);
        float4 v2 = __ldg(pre4 + (size_t)s2 * 32 + lane);
        float4 v3 = __ldg(pre4 + (size_t)s3 * 32 + lane);
        acc.x += v0.x + v1.x + v2.x + v3.x;
        acc.y += v0.y + v1.y + v2.y + v3.y;
        acc.z += v0.z + v1.z + v2.z + v3.z;
        acc.w += v0.w + v1.w + v2.w + v3.w;
    }
    for (; j < end; j++) {
        int s = __ldg(&g_csr[j]);
        float4 v = __ldg(pre4 + (size_t)s * 32 + lane);
        acc.x += v.x; acc.y += v.y; acc.z += v.z; acc.w += v.w;
    }

    *((float4*)(g_accum + (size_t)node * D) + lane) = acc;
}

// ---------------------------------------------------------------------------
// 4) GEMM (round-1 proven): out[n,128] = (g_accum[n,:]*g_inv[n]) @ W + b
//    Tail: zero g_deg / g_total for the next replay.
// ---------------------------------------------------------------------------
#define BM 128
#define BN 128
#define BK 16
#define TM 8
#define TN 8

__global__ __launch_bounds__(256, 2)
void gemm_kernel(const float* __restrict__ W,
                 const float* __restrict__ bias,
                 float* __restrict__ out,
                 int n) {
    __shared__ float As[BK][BM + 4];
    __shared__ float Ws[BK][BN];

    int block_row = blockIdx.x * BM;
    int tid = threadIdx.x;
    int tx = tid & 15;
    int ty = tid >> 4;

    float c[TM][TN];
#pragma unroll
    for (int i = 0; i < TM; i++)
#pragma unroll
        for (int j = 0; j < TN; j++) c[i][j] = 0.f;

    for (int k0 = 0; k0 < D; k0 += BK) {
#pragma unroll
        for (int it = 0; it < 2; it++) {
            int idx = tid + it * 256;
            int row = idx >> 2;
            int k4  = (idx & 3) * 4;
            int grow = block_row + row;
            float4 v = make_float4(0.f, 0.f, 0.f, 0.f);
            float iv = 0.f;
            if (grow < n) {
                v  = *(const float4*)&g_accum[(size_t)grow * D + k0 + k4];
                iv = g_inv[grow];
            }
            As[k4 + 0][row] = v.x * iv;
            As[k4 + 1][row] = v.y * iv;
            As[k4 + 2][row] = v.z * iv;
            As[k4 + 3][row] = v.w * iv;
        }
#pragma unroll
        for (int it = 0; it < 2; it++) {
            int idx = tid + it * 256;
            int k  = idx >> 5;
            int c4 = (idx & 31) * 4;
            float4 v = __ldg((const float4*)&W[(size_t)(k0 + k) * D + c4]);
            *(float4*)&Ws[k][c4] = v;
        }
        __syncthreads();

#pragma unroll
        for (int k = 0; k < BK; k++) {
            float a[TM], w[TN];
#pragma unroll
            for (int i = 0; i < TM; i++) a[i] = As[k][ty * TM + i];
#pragma unroll
            for (int j = 0; j < TN; j++) w[j] = Ws[k][tx * TN + j];
#pragma unroll
            for (int i = 0; i < TM; i++)
#pragma unroll
                for (int j = 0; j < TN; j++)
                    c[i][j] = fmaf(a[i], w[j], c[i][j]);
        }
        __syncthreads();
    }

#pragma unroll
    for (int i = 0; i < TM; i++) {
        int row = block_row + ty * TM + i;
        if (row < n) {
#pragma unroll
            for (int j = 0; j < TN; j += 4) {
                int col = tx * TN + j;
                float4 r;
                r.x = c[i][j + 0] + __ldg(&bias[col + 0]);
                r.y = c[i][j + 1] + __ldg(&bias[col + 1]);
                r.z = c[i][j + 2] + __ldg(&bias[col + 2]);
                r.w = c[i][j + 3] + __ldg(&bias[col + 3]);
                *(float4*)&out[(size_t)row * D + col] = r;
            }
        }
    }

    // Reset per-replay state for the next graph replay
    int gidx = blockIdx.x * blockDim.x + tid;
    if (gidx < n) g_deg[gidx] = 0;
    if (gidx == 0) g_total = 0;
}

// ---------------------------------------------------------------------------
extern "C" void kernel_launch(void* const* d_in, const int* in_sizes, int n_in,
                              void* d_out, int out_size) {
    const float* feature = (const float*)d_in[0];
    const float* W       = (const float*)d_in[1];
    const float* bias    = (const float*)d_in[2];
    const int*   src     = (const int*)d_in[3];
    const int*   dst     = (const int*)d_in[4];
    float*       out     = (float*)d_out;

    int N = in_sizes[0] / D;
    int E = in_sizes[3];

    // 0) in-degree
    deg_kernel<<<(E + 255) / 256, 256>>>(dst, E);
    // 1) pre-scale rows + inv + rowstart/cursor
    {
        long long total = (long long)N * 32;
        prep_kernel<<<(int)((total + 255) / 256), 256>>>(feature, N);
    }
    // 2) CSR fill
    fill_kernel<<<(E + 255) / 256, 256>>>(src, dst, E);
    // 3) gather aggregation  (profiled launch)
    {
        long long total = (long long)N * 32;
        agg_kernel<<<(int)((total + 255) / 256), 256>>>(N);
    }
    // 4) GEMM + bias (+ state reset)
    gemm_kernel<<<(N + BM - 1) / BM, 256>>>(W, bias, out, N);
}

// round 6
// speedup vs baseline: 28.3184x; 1.3790x over previous
#include <cuda_runtime.h>
#include <cuda_bf16.h>

#define D       128
#define MAXN    100000
#define MAXE    1600000

typedef unsigned long long u64;

// ---------------------------------------------------------------------------
// Scratch — static __device__ arrays, referenced ONLY inside kernels.
// (NEVER pass these as kernel args: host shadow symbol + GB300 ATS = silent
//  200GB/s NVLink-C2C traffic — the round-2/4 5ms regression.)
// ---------------------------------------------------------------------------
__device__ int   g_deg[MAXN];
__device__ float g_scale[MAXN];                    // rsqrt(deg+1)
__device__ float g_inv[MAXN];                      // 1/max(deg,1)
__device__ int   g_rowstart[MAXN];
__device__ int   g_cursor[MAXN];
__device__ int   g_csr[MAXE];                      // src ids grouped by dst
__device__ int   g_total;                          // rowstart allocator
__device__ float g_pre[(size_t)MAXN * D];          // (feat*scale) @ W  (51.2MB)

// ---------------------------------------------------------------------------
// 0) In-degree histogram (g_deg zeroed by previous replay's agg tail;
//    zero-initialized at module load for the first run)
// ---------------------------------------------------------------------------
__global__ void deg_kernel(const int* __restrict__ dst, int E) {
    int i = blockIdx.x * blockDim.x + threadIdx.x;
    if (i < E) atomicAdd(&g_deg[dst[i]], 1);
}

// ---------------------------------------------------------------------------
// 1) mini-prep: N threads. scale, inv, rowstart, cursor.
// ---------------------------------------------------------------------------
__global__ void prep_kernel(int N) {
    int i = blockIdx.x * blockDim.x + threadIdx.x;
    if (i >= N) return;
    int dg = g_deg[i];
    g_scale[i] = rsqrtf((float)dg + 1.0f);
    g_inv[i]   = 1.0f / (float)(dg > 0 ? dg : 1);
    int rs = atomicAdd(&g_total, dg);
    g_rowstart[i] = rs;
    g_cursor[i]   = rs;
}

// ---------------------------------------------------------------------------
// 2) CSR fill: bucket src by dst
// ---------------------------------------------------------------------------
__global__ void fill_kernel(const int* __restrict__ src,
                            const int* __restrict__ dst, int E) {
    int i = blockIdx.x * blockDim.x + threadIdx.x;
    if (i < E) {
        int p = atomicAdd(&g_cursor[dst[i]], 1);
        g_csr[p] = src[i];
    }
}

// ---------------------------------------------------------------------------
// 3) GEMM: g_pre[n,128] = (feature[n,:] * scale[n]) @ W[128,128]
//    Packed fma.rn.f32x2 inner loop (2 FMAs per fma-pipe issue, sm_10x).
//    NO minBlocks clause: let ptxas allocate registers freely (no spills).
// ---------------------------------------------------------------------------
#define BM 128
#define BN 128
#define BK 16
#define TM 8
#define TN 8

__device__ __forceinline__ u64 pack2(float lo, float hi) {
    u64 r;
    asm("mov.b64 %0, {%1,%2};" : "=l"(r) : "f"(lo), "f"(hi));
    return r;
}
__device__ __forceinline__ float2 unpack2(u64 v) {
    float2 r;
    asm("mov.b64 {%0,%1}, %2;" : "=f"(r.x), "=f"(r.y) : "l"(v));
    return r;
}
__device__ __forceinline__ void fma2(u64& c, u64 a, u64 b) {
    asm("fma.rn.f32x2 %0, %1, %2, %3;" : "=l"(c) : "l"(a), "l"(b), "l"(c));
}

__global__ __launch_bounds__(256)
void gemm_kernel(const float* __restrict__ feat,
                 const float* __restrict__ W,
                 int n) {
    __shared__ __align__(16) float As[BK][BM + 4];
    __shared__ __align__(16) float Ws[BK][BN];

    int block_row = blockIdx.x * BM;
    int tid = threadIdx.x;
    int tx = tid & 15;
    int ty = tid >> 4;

    u64 c2[TM][TN / 2];
#pragma unroll
    for (int i = 0; i < TM; i++)
#pragma unroll
        for (int j = 0; j < TN / 2; j++) c2[i][j] = 0ULL;

    for (int k0 = 0; k0 < D; k0 += BK) {
        // A tile (BM x BK) with scale applied at load
#pragma unroll
        for (int it = 0; it < 2; it++) {
            int idx = tid + it * 256;
            int row = idx >> 2;
            int k4  = (idx & 3) * 4;
            int grow = block_row + row;
            float4 v = make_float4(0.f, 0.f, 0.f, 0.f);
            float sc = 0.f;
            if (grow < n) {
                v  = __ldg((const float4*)&feat[(size_t)grow * D + k0 + k4]);
                sc = g_scale[grow];
            }
            As[k4 + 0][row] = v.x * sc;
            As[k4 + 1][row] = v.y * sc;
            As[k4 + 2][row] = v.z * sc;
            As[k4 + 3][row] = v.w * sc;
        }
        // W tile (BK x BN)
#pragma unroll
        for (int it = 0; it < 2; it++) {
            int idx = tid + it * 256;
            int k  = idx >> 5;
            int c4 = (idx & 31) * 4;
            float4 v = __ldg((const float4*)&W[(size_t)(k0 + k) * D + c4]);
            *(float4*)&Ws[k][c4] = v;
        }
        __syncthreads();

#pragma unroll
        for (int k = 0; k < BK; k++) {
            float a[TM];
            u64 wv[TN / 2];
#pragma unroll
            for (int i = 0; i < TM; i++) a[i] = As[k][ty * TM + i];
            const u64* wp = (const u64*)&Ws[k][tx * TN];
#pragma unroll
            for (int j = 0; j < TN / 2; j++) wv[j] = wp[j];
#pragma unroll
            for (int i = 0; i < TM; i++) {
                u64 ap = pack2(a[i], a[i]);
#pragma unroll
                for (int j = 0; j < TN / 2; j++)
                    fma2(c2[i][j], ap, wv[j]);
            }
        }
        __syncthreads();
    }

#pragma unroll
    for (int i = 0; i < TM; i++) {
        int row = block_row + ty * TM + i;
        if (row < n) {
            float2 p0 = unpack2(c2[i][0]);
            float2 p1 = unpack2(c2[i][1]);
            float2 p2 = unpack2(c2[i][2]);
            float2 p3 = unpack2(c2[i][3]);
            int col = tx * TN;
            *(float4*)&g_pre[(size_t)row * D + col]     = make_float4(p0.x, p0.y, p1.x, p1.y);
            *(float4*)&g_pre[(size_t)row * D + col + 4] = make_float4(p2.x, p2.y, p3.x, p3.y);
        }
    }
}

// ---------------------------------------------------------------------------
// 4) Aggregation (pure gather): one warp per dst node.
//    out[d,:] = inv[d] * sum_{s in nbr(d)} g_pre[s,:] + bias
//    Tail: zero g_deg / g_total for the next graph replay.
// ---------------------------------------------------------------------------
__global__ __launch_bounds__(256)
void agg_kernel(const float* __restrict__ bias,
                float* __restrict__ out,
                int N) {
    int t = blockIdx.x * blockDim.x + threadIdx.x;
    int node = t >> 5;
    int lane = t & 31;
    if (node >= N) return;

    int start = g_rowstart[node];
    int deg   = g_deg[node];
    int end   = start + deg;

    const float4* pre4 = (const float4*)g_pre;

    float4 acc = make_float4(0.f, 0.f, 0.f, 0.f);

    int j = start;
    for (; j + 3 < end; j += 4) {
        int s0 = __ldg(&g_csr[j + 0]);
        int s1 = __ldg(&g_csr[j + 1]);
        int s2 = __ldg(&g_csr[j + 2]);
        int s3 = __ldg(&g_csr[j + 3]);
        float4 v0 = __ldg(pre4 + (size_t)s0 * 32 + lane);
        float4 v1 = __ldg(pre4 + (size_t)s1 * 32 + lane);
        float4 v2 = __ldg(pre4 + (size_t)s2 * 32 + lane);
        float4 v3 = __ldg(pre4 + (size_t)s3 * 32 + lane);
        acc.x += v0.x + v1.x + v2.x + v3.x;
        acc.y += v0.y + v1.y + v2.y + v3.y;
        acc.z += v0.z + v1.z + v2.z + v3.z;
        acc.w += v0.w + v1.w + v2.w + v3.w;
    }
    for (; j < end; j++) {
        int s = __ldg(&g_csr[j]);
        float4 v = __ldg(pre4 + (size_t)s * 32 + lane);
        acc.x += v.x; acc.y += v.y; acc.z += v.z; acc.w += v.w;
    }

    float iv = g_inv[node];
    float4 bb = __ldg((const float4*)bias + lane);
    float4 r;
    r.x = acc.x * iv + bb.x;
    r.y = acc.y * iv + bb.y;
    r.z = acc.z * iv + bb.z;
    r.w = acc.w * iv + bb.w;
    *((float4*)(out + (size_t)node * D) + lane) = r;

    // Reset per-replay state (node-private: this warp already consumed deg)
    if (lane == 0) g_deg[node] = 0;
    if (t == 0)    g_total = 0;
}

// ---------------------------------------------------------------------------
extern "C" void kernel_launch(void* const* d_in, const int* in_sizes, int n_in,
                              void* d_out, int out_size) {
    const float* feature = (const float*)d_in[0];
    const float* W       = (const float*)d_in[1];
    const float* bias    = (const float*)d_in[2];
    const int*   src     = (const int*)d_in[3];
    const int*   dst     = (const int*)d_in[4];
    float*       out     = (float*)d_out;

    int N = in_sizes[0] / D;
    int E = in_sizes[3];

    deg_kernel<<<(E + 255) / 256, 256>>>(dst, E);
    prep_kernel<<<(N + 255) / 256, 256>>>(N);
    fill_kernel<<<(E + 255) / 256, 256>>>(src, dst, E);
    gemm_kernel<<<(N + BM - 1) / BM, 256>>>(feature, W, N);
    {
        long long total = (long long)N * 32;
        agg_kernel<<<(int)((total + 255) / 256), 256>>>(bias, out, N);
    }
}